// round 11
// baseline (speedup 1.0000x reference)
#include <cuda_runtime.h>

// TRFAligner: out[d, t] = sum over (seq, k) with sourceIdx[seq] + k == t of TRFs[seq, k, d]
// TRFs: (nSeq, nWin, OUTD) fp32; out: (OUTD, nRealLen) fp32. sourceIdx sorted.
// TILE_T=32 / 256 threads / 4 rows per warp. Inner loop unrolled by 2 seqs:
// 8 front-batched LDG.128 per iteration (MLP_p1=8), 32 warps/SM -> ~128KB
// in-flight per SM. Warp-cooperative ballot search. No atomics.

#define OUTD      128
#define TILE_T    32
#define ROWSTRIDE 132                 // (OUTD+4) floats, float4-aligned rows
#define NWARPS    8
#define NTHREADS  (NWARPS * 32)
#define ROWS_PW   (TILE_T / NWARPS)   // 4 rows per warp: tt = w + 8*r
#define CHUNK     64

// Warp-cooperative lower_bound: smallest i with a[i] >= v. All 32 lanes participate.
__device__ __forceinline__ int warp_lower_bound(const int* __restrict__ a,
                                                int n, int v, int lane)
{
    int lo = 0, hi = n;                       // answer in [lo, hi]
    while (hi - lo > 32) {
        const int chunk = (hi - lo + 32) / 33;
        const int p  = lo + (lane + 1) * chunk;
        const int pv = (p < hi) ? __ldg(a + p) : 0x7fffffff;
        const unsigned m = __ballot_sync(0xffffffffu, pv < v);
        const int c = __popc(m);              // probes strictly below v
        const int nlo = lo + c * chunk;
        hi = min(hi, nlo + chunk);
        lo = nlo;
    }
    const int p  = lo + lane;
    const int pv = (p < hi) ? __ldg(a + p) : 0x7fffffff;
    const unsigned m = __ballot_sync(0xffffffffu, pv < v);
    return lo + __popc(m);
}

__global__ __launch_bounds__(NTHREADS, 4) void trf_fold_kernel(
    const float4* __restrict__ TRF4,
    const int*    __restrict__ sIdx,
    float*        __restrict__ out,
    int nSeq, int nWin, int nRealLen)
{
    __shared__ float sm[TILE_T * ROWSTRIDE];
    __shared__ int   s_on[CHUNK];
    __shared__ int   s_range[2];

    const int t0   = blockIdx.x * TILE_T;
    const int tid  = threadIdx.x;
    const int w    = tid >> 5;
    const int lane = tid & 31;

    // ---- per-CTA range: warps 0 and 1 search concurrently (~3 ballot rounds each)
    if (w == 0) {
        int lo = warp_lower_bound(sIdx, nSeq, t0 - nWin + 1, lane);
        if (lane == 0) s_range[0] = lo;
    } else if (w == 1) {
        int hi = warp_lower_bound(sIdx, nSeq, t0 + TILE_T, lane);
        if (lane == 0) s_range[1] = hi;
    }
    __syncthreads();
    const int seqLo = s_range[0];
    const int seqHi = s_range[1];

    float4 acc[ROWS_PW];
    #pragma unroll
    for (int r = 0; r < ROWS_PW; ++r) acc[r] = make_float4(0.f, 0.f, 0.f, 0.f);

    const unsigned f4Row     = OUTD / 4;                 // 32 float4 per row
    const unsigned seqStride = (unsigned)nWin * f4Row;   // float4 per seq

    for (int cbase = seqLo; cbase < seqHi; cbase += CHUNK) {
        const int cn = min(seqHi - cbase, CHUNK);
        __syncthreads();                                 // protect s_on reuse
        if (tid < cn) s_on[tid] = sIdx[cbase + tid];
        __syncthreads();

        int sA = s_on[0];
        int sB = (cn > 1) ? s_on[1] : 0;
        int j = 0;
        // ---- main: two seqs per iteration, 8 front-batched LDG.128 ----
        while (j + 1 < cn) {
            const int sA_n = (j + 2 < cn) ? s_on[j + 2] : 0;   // prefetch next pair
            const int sB_n = (j + 3 < cn) ? s_on[j + 3] : 0;

            const int kb0 = t0 + w - sA;
            const int kb1 = t0 + w - sB;
            const unsigned off0 = (unsigned)(cbase + j)     * seqStride
                                + (unsigned)kb0 * f4Row + (unsigned)lane;
            const unsigned off1 = (unsigned)(cbase + j + 1) * seqStride
                                + (unsigned)kb1 * f4Row + (unsigned)lane;

            float4 v0[ROWS_PW], v1[ROWS_PW];
            bool   p0[ROWS_PW], p1[ROWS_PW];
            #pragma unroll
            for (int r = 0; r < ROWS_PW; ++r) {
                p0[r] = (unsigned)(kb0 + 8 * r) < (unsigned)nWin;
                v0[r] = make_float4(0.f, 0.f, 0.f, 0.f);
                if (p0[r]) v0[r] = __ldcs(&TRF4[off0 + r * 8 * f4Row]);
            }
            #pragma unroll
            for (int r = 0; r < ROWS_PW; ++r) {
                p1[r] = (unsigned)(kb1 + 8 * r) < (unsigned)nWin;
                v1[r] = make_float4(0.f, 0.f, 0.f, 0.f);
                if (p1[r]) v1[r] = __ldcs(&TRF4[off1 + r * 8 * f4Row]);
            }
            #pragma unroll
            for (int r = 0; r < ROWS_PW; ++r) {
                if (p0[r]) {
                    acc[r].x += v0[r].x; acc[r].y += v0[r].y;
                    acc[r].z += v0[r].z; acc[r].w += v0[r].w;
                }
            }
            #pragma unroll
            for (int r = 0; r < ROWS_PW; ++r) {
                if (p1[r]) {
                    acc[r].x += v1[r].x; acc[r].y += v1[r].y;
                    acc[r].z += v1[r].z; acc[r].w += v1[r].w;
                }
            }
            sA = sA_n; sB = sB_n;
            j += 2;
        }
        // ---- odd tail ----
        if (j < cn) {
            const int kb0 = t0 + w - sA;
            const unsigned off0 = (unsigned)(cbase + j) * seqStride
                                + (unsigned)kb0 * f4Row + (unsigned)lane;
            #pragma unroll
            for (int r = 0; r < ROWS_PW; ++r) {
                if ((unsigned)(kb0 + 8 * r) < (unsigned)nWin) {
                    float4 v = __ldcs(&TRF4[off0 + r * 8 * f4Row]);
                    acc[r].x += v.x; acc[r].y += v.y;
                    acc[r].z += v.z; acc[r].w += v.w;
                }
            }
        }
    }

    // ---- one smem pass for the transpose ----
    #pragma unroll
    for (int r = 0; r < ROWS_PW; ++r)
        *reinterpret_cast<float4*>(sm + (w + 8 * r) * ROWSTRIDE + lane * 4) = acc[r];
    __syncthreads();

    // ---- coalesced streaming store: consecutive tid -> consecutive t per d-row ----
    #pragma unroll
    for (int idx = tid; idx < OUTD * TILE_T; idx += NTHREADS) {
        const int d  = idx >> 5;              // / TILE_T
        const int tt = idx & (TILE_T - 1);
        const int t  = t0 + tt;
        if (t < nRealLen)
            __stcs(&out[(size_t)d * nRealLen + t], sm[tt * ROWSTRIDE + d]);
    }
}

extern "C" void kernel_launch(void* const* d_in, const int* in_sizes, int n_in,
                              void* d_out, int out_size)
{
    const float4* TRF4 = (const float4*)d_in[0];
    const int*    sIdx = (const int*)d_in[1];
    const int nSeq     = in_sizes[1];
    const int nWin     = in_sizes[0] / (nSeq * OUTD);
    const int nRealLen = out_size / OUTD;

    const int grid = (nRealLen + TILE_T - 1) / TILE_T;
    trf_fold_kernel<<<grid, NTHREADS>>>(TRF4, sIdx, (float*)d_out,
                                        nSeq, nWin, nRealLen);
}

// round 14
// speedup vs baseline: 1.2607x; 1.2607x over previous
#include <cuda_runtime.h>
#include <cstdint>

// TRFAligner: out[d, t] = sum over (seq, k) with sourceIdx[seq] + k == t of TRFs[seq, k, d]
// TRFs: (nSeq, nWin, OUTD) fp32; out: (OUTD, nRealLen) fp32. sourceIdx sorted.
// TILE_T=32 / 256 threads / 4 rows per warp. cp.async (LDGSTS) double-buffered
// stages: MLP held in the async queue instead of registers. Out-of-window rows:
// src-size=0 with address clamped to the base. CRITICAL: the element index is
// formed entirely in 32-bit unsigned so negative-kb wraparound cancels BEFORE
// the 64-bit pointer add. Barrier-free pipeline. No atomics.

#define OUTD      128
#define TILE_T    32
#define ROWSTRIDE 132                 // transpose tile row stride (floats)
#define NWARPS    8
#define NTHREADS  (NWARPS * 32)
#define ROWS_PW   (TILE_T / NWARPS)   // 4 rows per warp: tt = w + 8*r
#define CHUNK     64
#define STAGE_B   (TILE_T * 32 * 16)  // 32 rows * 512B = 16384 bytes per stage

__device__ __forceinline__ void cp_async16(uint32_t dst, const void* src, int sz) {
    asm volatile("cp.async.cg.shared.global [%0], [%1], 16, %2;\n"
                 :: "r"(dst), "l"(src), "r"(sz));
}
#define CP_COMMIT() asm volatile("cp.async.commit_group;\n" ::: "memory")
#define CP_WAIT(N)  asm volatile("cp.async.wait_group %0;\n" :: "n"(N) : "memory")

// Warp-cooperative lower_bound: smallest i with a[i] >= v. All 32 lanes participate.
__device__ __forceinline__ int warp_lower_bound(const int* __restrict__ a,
                                                int n, int v, int lane)
{
    int lo = 0, hi = n;
    while (hi - lo > 32) {
        const int chunk = (hi - lo + 32) / 33;
        const int p  = lo + (lane + 1) * chunk;
        const int pv = (p < hi) ? __ldg(a + p) : 0x7fffffff;
        const unsigned m = __ballot_sync(0xffffffffu, pv < v);
        const int c = __popc(m);
        const int nlo = lo + c * chunk;
        hi = min(hi, nlo + chunk);
        lo = nlo;
    }
    const int p  = lo + lane;
    const int pv = (p < hi) ? __ldg(a + p) : 0x7fffffff;
    const unsigned m = __ballot_sync(0xffffffffu, pv < v);
    return lo + __popc(m);
}

__global__ __launch_bounds__(NTHREADS, 6) void trf_fold_kernel(
    const float4* __restrict__ TRF4,
    const int*    __restrict__ sIdx,
    float*        __restrict__ out,
    int nSeq, int nWin, int nRealLen)
{
    // 2 cp.async stages; the transpose tile (32*132*4 = 16896B) aliases them later.
    __shared__ __align__(16) char raw[2 * STAGE_B];
    __shared__ int s_on[CHUNK];
    __shared__ int s_range[2];

    const int t0   = blockIdx.x * TILE_T;
    const int tid  = threadIdx.x;
    const int w    = tid >> 5;
    const int lane = tid & 31;

    const uint32_t stg_u32 = (uint32_t)__cvta_generic_to_shared(raw);
    uint32_t slot[ROWS_PW];               // this thread's 4 stage slots, 16B each
    #pragma unroll
    for (int r = 0; r < ROWS_PW; ++r)
        slot[r] = stg_u32 + (((w + 8 * r) * 32 + lane) << 4);

    // ---- per-CTA range: warps 0 and 1 search concurrently ----
    if (w == 0) {
        int lo = warp_lower_bound(sIdx, nSeq, t0 - nWin + 1, lane);
        if (lane == 0) s_range[0] = lo;
    } else if (w == 1) {
        int hi = warp_lower_bound(sIdx, nSeq, t0 + TILE_T, lane);
        if (lane == 0) s_range[1] = hi;
    }
    __syncthreads();
    const int seqLo = s_range[0];
    const int seqHi = s_range[1];

    float4 acc[ROWS_PW];
    #pragma unroll
    for (int r = 0; r < ROWS_PW; ++r) acc[r] = make_float4(0.f, 0.f, 0.f, 0.f);

    const unsigned f4Row     = OUTD / 4;
    const unsigned seqStride = (unsigned)nWin * f4Row;
    const float4* stg = reinterpret_cast<const float4*>(raw);   // [2][1024] float4

    for (int cbase = seqLo; cbase < seqHi; cbase += CHUNK) {
        const int cn = min(seqHi - cbase, CHUNK);
        __syncthreads();                                 // protect s_on + stage reuse
        if (tid < cn) s_on[tid] = sIdx[cbase + tid];
        __syncthreads();

        // prologue: issue seq 0 into stage 0
        {
            const int kb = t0 + w - s_on[0];
            const unsigned off = (unsigned)cbase * seqStride
                               + (unsigned)kb * f4Row + (unsigned)lane;
            #pragma unroll
            for (int r = 0; r < ROWS_PW; ++r) {
                const bool p = (unsigned)(kb + 8 * r) < (unsigned)nWin;
                const unsigned idx = off + (unsigned)(r * 8) * f4Row;  // 32-bit wrap cancels
                const float4* src = p ? (TRF4 + idx) : TRF4;
                cp_async16(slot[r], src, p ? 16 : 0);
            }
            CP_COMMIT();
        }

        for (int j = 0; j < cn; ++j) {
            if (j + 1 < cn) {
                const int kb = t0 + w - s_on[j + 1];
                const unsigned off = (unsigned)(cbase + j + 1) * seqStride
                                   + (unsigned)kb * f4Row + (unsigned)lane;
                const uint32_t sb = ((j + 1) & 1) * STAGE_B;
                #pragma unroll
                for (int r = 0; r < ROWS_PW; ++r) {
                    const bool p = (unsigned)(kb + 8 * r) < (unsigned)nWin;
                    const unsigned idx = off + (unsigned)(r * 8) * f4Row;
                    const float4* src = p ? (TRF4 + idx) : TRF4;
                    cp_async16(slot[r] + sb, src, p ? 16 : 0);
                }
                CP_COMMIT();
                CP_WAIT(1);                 // stage j complete, stage j+1 in flight
            } else {
                CP_WAIT(0);                 // drain
            }
            // accumulate stage j (zero-filled where out of window -> unguarded)
            const float4* buf = stg + (j & 1) * (STAGE_B / 16);
            #pragma unroll
            for (int r = 0; r < ROWS_PW; ++r) {
                const float4 v = buf[(w + 8 * r) * 32 + lane];
                acc[r].x += v.x; acc[r].y += v.y;
                acc[r].z += v.z; acc[r].w += v.w;
            }
        }
    }

    // ---- transpose: reuse stage smem (all pipeline reads done; barrier first) ----
    __syncthreads();
    float* sm = reinterpret_cast<float*>(raw);
    #pragma unroll
    for (int r = 0; r < ROWS_PW; ++r)
        *reinterpret_cast<float4*>(sm + (w + 8 * r) * ROWSTRIDE + lane * 4) = acc[r];
    __syncthreads();

    // ---- coalesced streaming store: consecutive tid -> consecutive t per d-row ----
    #pragma unroll
    for (int idx = tid; idx < OUTD * TILE_T; idx += NTHREADS) {
        const int d  = idx >> 5;              // / TILE_T
        const int tt = idx & (TILE_T - 1);
        const int t  = t0 + tt;
        if (t < nRealLen)
            __stcs(&out[(size_t)d * nRealLen + t], sm[tt * ROWSTRIDE + d]);
    }
}

extern "C" void kernel_launch(void* const* d_in, const int* in_sizes, int n_in,
                              void* d_out, int out_size)
{
    const float4* TRF4 = (const float4*)d_in[0];
    const int*    sIdx = (const int*)d_in[1];
    const int nSeq     = in_sizes[1];
    const int nWin     = in_sizes[0] / (nSeq * OUTD);
    const int nRealLen = out_size / OUTD;

    const int grid = (nRealLen + TILE_T - 1) / TILE_T;
    trf_fold_kernel<<<grid, NTHREADS>>>(TRF4, sIdx, (float*)d_out,
                                        nSeq, nWin, nRealLen);
}

// round 15
// speedup vs baseline: 1.2682x; 1.0060x over previous
#include <cuda_runtime.h>
#include <cstdint>

// TRFAligner: out[d, t] = sum over (seq, k) with sourceIdx[seq] + k == t of TRFs[seq, k, d]
// TRFs: (nSeq, nWin, OUTD) fp32; out: (OUTD, nRealLen) fp32. sourceIdx sorted.
// TILE_T=32 / 256 threads / 4 rows per warp. cp.async TRIPLE-buffered stages
// (issue distance 2, wait_group(2), one committed group per iteration — empty
// groups keep the count uniform). 32-bit unsigned element indexing so negative
// kb wraps cancel before the 64-bit pointer add. Barrier-free pipeline. No atomics.

#define OUTD      128
#define TILE_T    32
#define ROWSTRIDE 132                 // transpose tile row stride (floats)
#define NWARPS    8
#define NTHREADS  (NWARPS * 32)
#define ROWS_PW   (TILE_T / NWARPS)   // 4 rows per warp: tt = w + 8*r
#define CHUNK     64
#define NSTAGE    3
#define STAGE_B   (TILE_T * 32 * 16)  // 32 rows * 512B = 16384 bytes per stage

__device__ __forceinline__ void cp_async16(uint32_t dst, const void* src, int sz) {
    asm volatile("cp.async.cg.shared.global [%0], [%1], 16, %2;\n"
                 :: "r"(dst), "l"(src), "r"(sz));
}
#define CP_COMMIT() asm volatile("cp.async.commit_group;\n" ::: "memory")
#define CP_WAIT(N)  asm volatile("cp.async.wait_group %0;\n" :: "n"(N) : "memory")

// Warp-cooperative lower_bound: smallest i with a[i] >= v. All 32 lanes participate.
__device__ __forceinline__ int warp_lower_bound(const int* __restrict__ a,
                                                int n, int v, int lane)
{
    int lo = 0, hi = n;
    while (hi - lo > 32) {
        const int chunk = (hi - lo + 32) / 33;
        const int p  = lo + (lane + 1) * chunk;
        const int pv = (p < hi) ? __ldg(a + p) : 0x7fffffff;
        const unsigned m = __ballot_sync(0xffffffffu, pv < v);
        const int c = __popc(m);
        const int nlo = lo + c * chunk;
        hi = min(hi, nlo + chunk);
        lo = nlo;
    }
    const int p  = lo + lane;
    const int pv = (p < hi) ? __ldg(a + p) : 0x7fffffff;
    const unsigned m = __ballot_sync(0xffffffffu, pv < v);
    return lo + __popc(m);
}

__global__ __launch_bounds__(NTHREADS, 4) void trf_fold_kernel(
    const float4* __restrict__ TRF4,
    const int*    __restrict__ sIdx,
    float*        __restrict__ out,
    int nSeq, int nWin, int nRealLen)
{
    // 3 cp.async stages; transpose tile (16896B) aliases them after the drain.
    __shared__ __align__(16) char raw[NSTAGE * STAGE_B];
    __shared__ int s_on[CHUNK];
    __shared__ int s_range[2];

    const int t0   = blockIdx.x * TILE_T;
    const int tid  = threadIdx.x;
    const int w    = tid >> 5;
    const int lane = tid & 31;

    const uint32_t stg_u32 = (uint32_t)__cvta_generic_to_shared(raw);
    uint32_t slot[ROWS_PW];               // this thread's 4 stage-0 slots, 16B each
    #pragma unroll
    for (int r = 0; r < ROWS_PW; ++r)
        slot[r] = stg_u32 + (((w + 8 * r) * 32 + lane) << 4);

    // ---- per-CTA range: warps 0 and 1 search concurrently ----
    if (w == 0) {
        int lo = warp_lower_bound(sIdx, nSeq, t0 - nWin + 1, lane);
        if (lane == 0) s_range[0] = lo;
    } else if (w == 1) {
        int hi = warp_lower_bound(sIdx, nSeq, t0 + TILE_T, lane);
        if (lane == 0) s_range[1] = hi;
    }
    __syncthreads();
    const int seqLo = s_range[0];
    const int seqHi = s_range[1];

    float4 acc[ROWS_PW];
    #pragma unroll
    for (int r = 0; r < ROWS_PW; ++r) acc[r] = make_float4(0.f, 0.f, 0.f, 0.f);

    const unsigned f4Row     = OUTD / 4;
    const unsigned seqStride = (unsigned)nWin * f4Row;
    const float4* stg = reinterpret_cast<const float4*>(raw);

    for (int cbase = seqLo; cbase < seqHi; cbase += CHUNK) {
        const int cn = min(seqHi - cbase, CHUNK);
        __syncthreads();                                 // protect s_on + stage reuse
        if (tid < cn) s_on[tid] = sIdx[cbase + tid];
        __syncthreads();

        // issue helper (macro-free lambda): one seq into stage (q % NSTAGE)
        auto issue = [&](int q) {
            const int kb = t0 + w - s_on[q];
            const unsigned off = (unsigned)(cbase + q) * seqStride
                               + (unsigned)kb * f4Row + (unsigned)lane;
            const uint32_t sb = (uint32_t)(q % NSTAGE) * STAGE_B;
            #pragma unroll
            for (int r = 0; r < ROWS_PW; ++r) {
                const bool p = (unsigned)(kb + 8 * r) < (unsigned)nWin;
                const unsigned idx = off + (unsigned)(r * 8) * f4Row;  // 32-bit wrap cancels
                const float4* src = p ? (TRF4 + idx) : TRF4;
                cp_async16(slot[r] + sb, src, p ? 16 : 0);
            }
        };

        // prologue: 2 groups (possibly empty) so the count stays uniform
        if (cn > 0) issue(0);
        CP_COMMIT();
        if (cn > 1) issue(1);
        CP_COMMIT();

        for (int j = 0; j < cn; ++j) {
            if (j + 2 < cn) issue(j + 2);
            CP_COMMIT();                    // exactly one group per iteration
            CP_WAIT(2);                     // all groups except last 2 done -> stage j ready
            const float4* buf = stg + (uint32_t)(j % NSTAGE) * (STAGE_B / 16);
            #pragma unroll
            for (int r = 0; r < ROWS_PW; ++r) {
                const float4 v = buf[(w + 8 * r) * 32 + lane];
                acc[r].x += v.x; acc[r].y += v.y;
                acc[r].z += v.z; acc[r].w += v.w;
            }
        }
        CP_WAIT(0);                         // drain before smem reuse
    }

    // ---- transpose: reuse stage smem ----
    __syncthreads();
    float* sm = reinterpret_cast<float*>(raw);
    #pragma unroll
    for (int r = 0; r < ROWS_PW; ++r)
        *reinterpret_cast<float4*>(sm + (w + 8 * r) * ROWSTRIDE + lane * 4) = acc[r];
    __syncthreads();

    // ---- coalesced streaming store: consecutive tid -> consecutive t per d-row ----
    #pragma unroll
    for (int idx = tid; idx < OUTD * TILE_T; idx += NTHREADS) {
        const int d  = idx >> 5;              // / TILE_T
        const int tt = idx & (TILE_T - 1);
        const int t  = t0 + tt;
        if (t < nRealLen)
            __stcs(&out[(size_t)d * nRealLen + t], sm[tt * ROWSTRIDE + d]);
    }
}

extern "C" void kernel_launch(void* const* d_in, const int* in_sizes, int n_in,
                              void* d_out, int out_size)
{
    const float4* TRF4 = (const float4*)d_in[0];
    const int*    sIdx = (const int*)d_in[1];
    const int nSeq     = in_sizes[1];
    const int nWin     = in_sizes[0] / (nSeq * OUTD);
    const int nRealLen = out_size / OUTD;

    const int grid = (nRealLen + TILE_T - 1) / TILE_T;
    trf_fold_kernel<<<grid, NTHREADS>>>(TRF4, sIdx, (float*)d_out,
                                        nSeq, nWin, nRealLen);
}